// round 15
// baseline (speedup 1.0000x reference)
#include <cuda_runtime.h>

// Fixed shapes from reference: [16, 2, 768, 768], NUM_IT=4
#define Nn    16
#define Hh    768
#define Ww    768
#define HW    (Hh * Ww)        // 589824
#define NHW   (Nn * HW)        // 9437184
#define NPIX4 (NHW / 4)        // 4 pixels per thread

// Ping-pong scratch, interleaved float2 [N,H,W] (75.5 MB each).
__device__ static float2 g_bufA[NHW];
__device__ static float2 g_bufB[NHW];

__device__ __forceinline__ int clamp0(int v, int hi) {
    return v < 0 ? 0 : (v > hi ? hi : v);
}

// ---------------------------------------------------------------------------
// Iteration 0: planar input [N,2,H,W] -> interleaved float2 scratch.
// Also writes pred_cent plane 0 (= n, constant) and zeroes num_touch,
// moving 76MB of streaming stores off the tail kernel.
// Gathers bypass L1 (__ldcg): random over a 4.7MB plane, L1 hit ~0.
// ---------------------------------------------------------------------------
__global__ __launch_bounds__(256) void iter_first(const float* __restrict__ in,
                                                  float2* __restrict__ out,
                                                  float* __restrict__ touch,
                                                  float* __restrict__ cent) {
    int t = blockIdx.x * blockDim.x + threadIdx.x;
    if (t >= NPIX4) return;
    int idx = t * 4;
    int n   = idx / HW;
    int rem = idx - n * HW;
    int y   = rem / Ww;
    int x   = rem - y * Ww;            // rem % 4 == 0, x+3 < Ww (Ww % 4 == 0)

    const float* base = in + (size_t)n * (2 * HW);
    float4 dx4 = *(const float4*)(base + rem);
    float4 dy4 = *(const float4*)(base + HW + rem);

    int cx0 = clamp0((int)((float)(x + 0) + dx4.x), Ww - 1);
    int cx1 = clamp0((int)((float)(x + 1) + dx4.y), Ww - 1);
    int cx2 = clamp0((int)((float)(x + 2) + dx4.z), Ww - 1);
    int cx3 = clamp0((int)((float)(x + 3) + dx4.w), Ww - 1);
    int cy0 = clamp0((int)((float)y + dy4.x), Hh - 1);
    int cy1 = clamp0((int)((float)y + dy4.y), Hh - 1);
    int cy2 = clamp0((int)((float)y + dy4.z), Hh - 1);
    int cy3 = clamp0((int)((float)y + dy4.w), Hh - 1);
    int gi0 = cy0 * Ww + cx0, gi1 = cy1 * Ww + cx1;
    int gi2 = cy2 * Ww + cx2, gi3 = cy3 * Ww + cx3;

    // 8 independent scattered loads, L2-only
    float gx0 = __ldcg(base + gi0), gx1 = __ldcg(base + gi1);
    float gx2 = __ldcg(base + gi2), gx3 = __ldcg(base + gi3);
    float gy0 = __ldcg(base + HW + gi0), gy1 = __ldcg(base + HW + gi1);
    float gy2 = __ldcg(base + HW + gi2), gy3 = __ldcg(base + HW + gi3);

    // Scratch stores: DEFAULT policy — this is next pass's gather source,
    // must stay L2-resident (75MB fits in 126MB L2).
    *(float4*)&out[idx]     = make_float4(dx4.x + gx0, dy4.x + gy0,
                                          dx4.y + gx1, dy4.y + gy1);
    *(float4*)&out[idx + 2] = make_float4(dx4.z + gx2, dy4.z + gy2,
                                          dx4.w + gx3, dy4.w + gy3);

    // pred_cent plane 0 = batch index (constant): write-once output
    float fn = (float)n;
    __stcs((float4*)&cent[(size_t)n * (3 * HW) + rem],
           make_float4(fn, fn, fn, fn));
    // zero num_touch (default policy: atomics will hit these lines)
    *(float4*)&touch[idx] = make_float4(0.f, 0.f, 0.f, 0.f);
}

// ---------------------------------------------------------------------------
// Iterations 1,2: interleaved -> interleaved, 4 px/thread, 4 scattered 8B gathers.
// ---------------------------------------------------------------------------
__global__ __launch_bounds__(256) void iter_mid(const float2* __restrict__ in,
                                                float2* __restrict__ out) {
    int t = blockIdx.x * blockDim.x + threadIdx.x;
    if (t >= NPIX4) return;
    int idx = t * 4;
    int n   = idx / HW;
    int rem = idx - n * HW;
    int y   = rem / Ww;
    int x   = rem - y * Ww;

    float4 d01 = *(const float4*)&in[idx];      // (dx0,dy0,dx1,dy1)
    float4 d23 = *(const float4*)&in[idx + 2];  // (dx2,dy2,dx3,dy3)

    int cx0 = clamp0((int)((float)(x + 0) + d01.x), Ww - 1);
    int cy0 = clamp0((int)((float)y + d01.y), Hh - 1);
    int cx1 = clamp0((int)((float)(x + 1) + d01.z), Ww - 1);
    int cy1 = clamp0((int)((float)y + d01.w), Hh - 1);
    int cx2 = clamp0((int)((float)(x + 2) + d23.x), Ww - 1);
    int cy2 = clamp0((int)((float)y + d23.y), Hh - 1);
    int cx3 = clamp0((int)((float)(x + 3) + d23.z), Ww - 1);
    int cy3 = clamp0((int)((float)y + d23.w), Hh - 1);

    const float2* plane = in + n * HW;
    float2 g0 = __ldcg(&plane[cy0 * Ww + cx0]);
    float2 g1 = __ldcg(&plane[cy1 * Ww + cx1]);
    float2 g2 = __ldcg(&plane[cy2 * Ww + cx2]);
    float2 g3 = __ldcg(&plane[cy3 * Ww + cx3]);

    *(float4*)&out[idx]     = make_float4(d01.x + g0.x, d01.y + g0.y,
                                          d01.z + g1.x, d01.w + g1.y);
    *(float4*)&out[idx + 2] = make_float4(d23.x + g2.x, d23.y + g2.y,
                                          d23.z + g3.x, d23.w + g3.y);
}

// ---------------------------------------------------------------------------
// Iteration 3 (last): disp (planar, __stcs), num_touch (atomics),
// pred_cent planes 1,2 (__stcs). Plane 0 already written by iter_first.
// Atomics issued right after gathers so their wavefronts overlap store traffic.
// ---------------------------------------------------------------------------
__global__ __launch_bounds__(256) void iter_last(const float2* __restrict__ in,
                                                 float* __restrict__ out_disp,
                                                 float* __restrict__ num_touch,
                                                 float* __restrict__ pred_cent) {
    int t = blockIdx.x * blockDim.x + threadIdx.x;
    if (t >= NPIX4) return;
    int idx = t * 4;
    int n   = idx / HW;
    int rem = idx - n * HW;
    int y   = rem / Ww;
    int x   = rem - y * Ww;

    float4 d01 = *(const float4*)&in[idx];
    float4 d23 = *(const float4*)&in[idx + 2];

    int cx0 = clamp0((int)((float)(x + 0) + d01.x), Ww - 1);
    int cy0 = clamp0((int)((float)y + d01.y), Hh - 1);
    int cx1 = clamp0((int)((float)(x + 1) + d01.z), Ww - 1);
    int cy1 = clamp0((int)((float)y + d01.w), Hh - 1);
    int cx2 = clamp0((int)((float)(x + 2) + d23.x), Ww - 1);
    int cy2 = clamp0((int)((float)y + d23.y), Hh - 1);
    int cx3 = clamp0((int)((float)(x + 3) + d23.z), Ww - 1);
    int cy3 = clamp0((int)((float)y + d23.w), Hh - 1);

    // Issue all scattered ops (4 gathers + 4 atomics) up front for max MLP;
    // atomics have no return dependency so they retire independently.
    const float2* plane = in + n * HW;
    float2 g0 = __ldcg(&plane[cy0 * Ww + cx0]);
    float2 g1 = __ldcg(&plane[cy1 * Ww + cx1]);
    float2 g2 = __ldcg(&plane[cy2 * Ww + cx2]);
    float2 g3 = __ldcg(&plane[cy3 * Ww + cx3]);

    float* tplane = num_touch + n * HW;
    atomicAdd(&tplane[cy0 * Ww + cx0], 1.0f);
    atomicAdd(&tplane[cy1 * Ww + cx1], 1.0f);
    atomicAdd(&tplane[cy2 * Ww + cx2], 1.0f);
    atomicAdd(&tplane[cy3 * Ww + cx3], 1.0f);

    // pred_cent planes 1 (cx), 2 (cy): no dependency on gathers, store first
    size_t pb = (size_t)n * (3 * HW) + rem;
    __stcs((float4*)&pred_cent[pb + HW],
           make_float4((float)cx0, (float)cx1, (float)cx2, (float)cx3));
    __stcs((float4*)&pred_cent[pb + 2 * HW],
           make_float4((float)cy0, (float)cy1, (float)cy2, (float)cy3));

    // disp planar [N,2,H,W], write-once (consumes gather results)
    size_t db = (size_t)n * (2 * HW) + rem;
    __stcs((float4*)&out_disp[db],
           make_float4(d01.x + g0.x, d01.z + g1.x, d23.x + g2.x, d23.z + g3.x));
    __stcs((float4*)&out_disp[db + HW],
           make_float4(d01.y + g0.y, d01.w + g1.y, d23.y + g2.y, d23.w + g3.y));
}

extern "C" void kernel_launch(void* const* d_in, const int* in_sizes, int n_in,
                              void* d_out, int out_size) {
    (void)in_sizes; (void)n_in; (void)out_size;
    const float* pred_disp = (const float*)d_in[0];
    float* out = (float*)d_out;

    // Output layout: disp [N*2*H*W] | num_touch [N*H*W] | pred_cent [N*3*H*W]
    float* out_disp  = out;
    float* out_touch = out + (size_t)2 * NHW;
    float* out_cent  = out_touch + NHW;

    float2 *bufA = nullptr, *bufB = nullptr;
    cudaGetSymbolAddress((void**)&bufA, g_bufA);
    cudaGetSymbolAddress((void**)&bufB, g_bufB);

    const int threads = 256;
    const int blocks  = (NPIX4 + threads - 1) / threads;   // 9216

    iter_first<<<blocks, threads>>>(pred_disp, bufA, out_touch, out_cent); // it 0
    iter_mid  <<<blocks, threads>>>(bufA, bufB);                           // it 1
    iter_mid  <<<blocks, threads>>>(bufB, bufA);                           // it 2
    iter_last <<<blocks, threads>>>(bufA, out_disp, out_touch, out_cent);  // it 3
}